// round 12
// baseline (speedup 1.0000x reference)
#include <cuda_runtime.h>
#include <cstdint>

// Cost volume: out[b,k,h,w] = (1/81) * sum_c x1[b,c,h,w] * x2[b,c,h-i,w-j]
//   i,j in [-4,4], k = (9i+j) mod 81. Zero padding. B=4,C=128,H=128,W=256,D=81.
//
// R11 = R9 (best: 92.3us, 84% of the FFMA rt=2 wall of ~75us) with the inner
// loop software-pipelined: the 3 LDS.128 for window u+1 issue before the 36
// FMAs of window u retire (dep distance >> 29-cyc LDS latency), and s2
// addressing is strength-reduced to one base pointer per (st,cc) with
// constant row offsets. Geometry/pipeline unchanged: 192 thr = 3 groups x 64,
// group g owns di in {3g..3g+2}; 4h x 64w; CC=4 single-barrier cp.async
// double buffer; launch_bounds(192,2).

#define Bn 4
#define Cn 128
#define Hn 128
#define Wn 256
#define Dn 81
#define TH 4
#define TW 64
#define CC 4
#define NCH (Cn / CC)       // 32 chunks
#define S2H (TH + 8)        // 12
#define S2W (TW + 8)        // 72
#define NTHR 192

#define S1_F4 (CC * TH * TW / 4)    // 256
#define S2_F4 (CC * S2H * S2W / 4)  // 864

__device__ __forceinline__ void cp16(uint32_t saddr, const float* gptr, bool ok) {
    int sz = ok ? 16 : 0;
    asm volatile("cp.async.cg.shared.global [%0], [%1], 16, %2;\n"
                 :: "r"(saddr), "l"(gptr), "r"(sz));
}
__device__ __forceinline__ void cp_commit() {
    asm volatile("cp.async.commit_group;\n" ::: "memory");
}
template <int N>
__device__ __forceinline__ void cp_wait() {
    asm volatile("cp.async.wait_group %0;\n" :: "n"(N) : "memory");
}

__global__ __launch_bounds__(NTHR, 2)
void costvol_kernel(const float* __restrict__ x1,
                    const float* __restrict__ x2,
                    float* __restrict__ out) {
    __shared__ __align__(16) float s1[2][CC][TH][TW];   // 2 * 4 KB
    __shared__ __align__(16) float s2[2][CC][S2H][S2W]; // 2 * 13.5 KB

    const int w0 = blockIdx.x * TW;
    const int h0 = blockIdx.y * TH;
    const int b  = blockIdx.z;

    const int tid = threadIdx.x;
    const int g   = tid / 64;        // i-group 0..2
    const int r   = tid - g * 64;
    const int tx  = r & 15;          // 16 pixel-quads across w
    const int ty  = r >> 4;          // 4 rows

    const float* x1b = x1 + (size_t)(b * Cn) * Hn * Wn;
    const float* x2b = x2 + (size_t)(b * Cn) * Hn * Wn;

    auto prefetch = [&](int c0, int st) {
        // s1: 256 float4
#pragma unroll
        for (int q = 0; q < 2; q++) {
            int f = tid + q * NTHR;
            if (f < S1_F4) {
                int cc  = f >> 6;
                int rem = f & 63;
                int hh  = rem >> 4;
                int k4  = rem & 15;
                uint32_t sa = (uint32_t)__cvta_generic_to_shared(&s1[st][cc][hh][4 * k4]);
                cp16(sa, x1b + (((size_t)(c0 + cc) * Hn + h0 + hh) * Wn + w0 + 4 * k4), true);
            }
        }
        // s2: 864 float4
#pragma unroll
        for (int q = 0; q < 5; q++) {
            int f = tid + q * NTHR;
            if (f < S2_F4) {
                int cc  = f / (S2H * (S2W / 4));
                int rem = f - cc * (S2H * (S2W / 4));
                int row = rem / (S2W / 4);
                int k4  = rem - row * (S2W / 4);
                int hg  = h0 - 4 + row;
                int wg  = w0 - 4 + 4 * k4;
                bool ok = ((unsigned)hg < (unsigned)Hn) && ((unsigned)wg < (unsigned)Wn);
                const float* gp = ok ? (x2b + (((size_t)cc + c0) * Hn + hg) * (size_t)Wn + wg)
                                     : x2b;
                uint32_t sa = (uint32_t)__cvta_generic_to_shared(&s2[st][cc][row][4 * k4]);
                cp16(sa, gp, ok);
            }
        }
        cp_commit();
    };

    float acc[3][9][4];
#pragma unroll
    for (int u = 0; u < 3; u++)
#pragma unroll
        for (int jj = 0; jj < 9; jj++)
#pragma unroll
            for (int p = 0; p < 4; p++) acc[u][jj][p] = 0.f;

    // Per-thread constant smem float-offsets (strength reduction).
    const int s1off = ty * TW + 4 * tx;                     // within s1[st][cc]
    const int s2off = (ty + 8 - 3 * g) * S2W + 4 * tx;      // u=0 row within s2[st][cc]

    prefetch(0, 0);

    for (int it = 0; it < NCH; it++) {
        const int st = it & 1;
        cp_wait<0>();
        // Single barrier: publishes chunk `it` AND proves all readers of
        // stage st^1 are done, so the refill below is race-free.
        __syncthreads();
        if (it + 1 < NCH) prefetch((it + 1) * CC, st ^ 1);

        const float* s1base = &s1[st][0][0][0];
        const float* s2base = &s2[st][0][0][0];

#pragma unroll
        for (int cc = 0; cc < CC; cc++) {
            const float4 av = *(const float4*)(s1base + cc * (TH * TW) + s1off);
            const float a[4] = {av.x, av.y, av.z, av.w};
            const float* rp0 = s2base + cc * (S2H * S2W) + s2off;  // u=0 row

            // Preload window for u=0.
            float4 q0 = *(const float4*)(rp0);
            float4 q1 = *(const float4*)(rp0 + 4);
            float4 q2 = *(const float4*)(rp0 + 8);

#pragma unroll
            for (int u = 0; u < 3; u++) {
                // Issue next window's loads BEFORE consuming current window.
                float4 n0, n1, n2;
                if (u < 2) {
                    const float* rn = rp0 - (u + 1) * S2W;  // row for u+1
                    n0 = *(const float4*)(rn);
                    n1 = *(const float4*)(rn + 4);
                    n2 = *(const float4*)(rn + 8);
                }
                const float wnd[12] = {q0.x, q0.y, q0.z, q0.w,
                                       q1.x, q1.y, q1.z, q1.w,
                                       q2.x, q2.y, q2.z, q2.w};
#pragma unroll
                for (int jj = 0; jj < 9; jj++) {
#pragma unroll
                    for (int p = 0; p < 4; p++)
                        acc[u][jj][p] += a[p] * wnd[p + 8 - jj];
                }
                if (u < 2) { q0 = n0; q1 = n1; q2 = n2; }
            }
        }
    }

    // ---- epilogue: k = (9*ii + jj + 41) mod 81, ii = 3g+u ----
    const float inv = 1.0f / 81.0f;
    const int hg = h0 + ty;
    const int wg = w0 + 4 * tx;
#pragma unroll
    for (int u = 0; u < 3; u++) {
        const int ii = 3 * g + u;
#pragma unroll
        for (int jj = 0; jj < 9; jj++) {
            int k = 9 * ii + jj + 41;
            if (k >= 81) k -= 81;
            float4 v = make_float4(acc[u][jj][0] * inv, acc[u][jj][1] * inv,
                                   acc[u][jj][2] * inv, acc[u][jj][3] * inv);
            *(float4*)(out + (((size_t)((b * Dn + k) * Hn + hg)) * Wn + wg)) = v;
        }
    }
}

extern "C" void kernel_launch(void* const* d_in, const int* in_sizes, int n_in,
                              void* d_out, int out_size) {
    (void)in_sizes; (void)n_in; (void)out_size;
    const float* x1 = (const float*)d_in[0];
    const float* x2 = (const float*)d_in[1];
    float* out = (float*)d_out;
    dim3 grid(Wn / TW, Hn / TH, Bn);   // (4, 32, 4) = 512 blocks
    costvol_kernel<<<grid, NTHR>>>(x1, x2, out);
}